// round 2
// baseline (speedup 1.0000x reference)
#include <cuda_runtime.h>

#define B_BATCH 2
#define SEQ 2048
#define EMBED 1024
#define HEADS 16
#define HDIM 64
#define MROWS (B_BATCH * SEQ)   // 4096

// ---------------- scratch (device globals: allocation-free) ----------------
__device__ float g_Q[(size_t)MROWS * EMBED];
__device__ float g_K[(size_t)MROWS * EMBED];
__device__ float g_V[(size_t)MROWS * EMBED];
__device__ float g_O[(size_t)MROWS * EMBED];
__device__ float g_S[(size_t)B_BATCH * HEADS * SEQ * SEQ];   // 512 MB logits/probs
__device__ float g_qsq[(size_t)B_BATCH * HEADS * SEQ];
__device__ float g_ksq[(size_t)B_BATCH * HEADS * SEQ];

// row/col split-fragment mapping: thread covers rows {ty*4..+3, 64+ty*4..+3}
__device__ __forceinline__ int frag_idx(int base4, int i) {
    return (i < 4) ? (base4 * 4 + i) : (64 + base4 * 4 + (i - 4));
}

// ---------------- generic SGEMM: C = A[MxK] @ B[KxN] + bias ----------------
// 128x128 tile, BK=16, 256 threads, 8x8 per thread (split fragments)
__global__ __launch_bounds__(256) void sgemm_bias_kernel(
    const float* __restrict__ A, const float* __restrict__ Bm,
    const float* __restrict__ bias, float* __restrict__ C,
    int M, int N, int K)
{
    __shared__ float As[16][128];
    __shared__ float Bs[16][128];
    const int tid = threadIdx.x;
    const int tx = tid % 16, ty = tid / 16;
    const int brow = blockIdx.y * 128;
    const int bcol = blockIdx.x * 128;

    float acc[8][8];
#pragma unroll
    for (int i = 0; i < 8; i++)
#pragma unroll
        for (int j = 0; j < 8; j++) acc[i][j] = 0.f;

    for (int k0 = 0; k0 < K; k0 += 16) {
        // A tile 128x16 -> transposed store
#pragma unroll
        for (int it = 0; it < 2; it++) {
            int idx = tid + it * 256;      // 0..511 float4s
            int r = idx >> 2;              // 0..127
            int c4 = idx & 3;              // 0..3
            float4 v = *(const float4*)&A[(size_t)(brow + r) * K + k0 + c4 * 4];
            As[c4 * 4 + 0][r] = v.x; As[c4 * 4 + 1][r] = v.y;
            As[c4 * 4 + 2][r] = v.z; As[c4 * 4 + 3][r] = v.w;
        }
        // B tile 16x128 -> direct store
#pragma unroll
        for (int it = 0; it < 2; it++) {
            int idx = tid + it * 256;
            int r = idx >> 5;              // 0..15
            int c4 = idx & 31;             // 0..31
            *(float4*)&Bs[r][c4 * 4] =
                *(const float4*)&Bm[(size_t)(k0 + r) * N + bcol + c4 * 4];
        }
        __syncthreads();
#pragma unroll
        for (int k = 0; k < 16; k++) {
            float a[8], b[8];
            *(float4*)&a[0] = *(const float4*)&As[k][ty * 4];
            *(float4*)&a[4] = *(const float4*)&As[k][64 + ty * 4];
            *(float4*)&b[0] = *(const float4*)&Bs[k][tx * 4];
            *(float4*)&b[4] = *(const float4*)&Bs[k][64 + tx * 4];
#pragma unroll
            for (int i = 0; i < 8; i++)
#pragma unroll
                for (int j = 0; j < 8; j++) acc[i][j] += a[i] * b[j];
        }
        __syncthreads();
    }

    float bv0[4], bv1[4];
    *(float4*)&bv0[0] = *(const float4*)&bias[bcol + tx * 4];
    *(float4*)&bv1[0] = *(const float4*)&bias[bcol + 64 + tx * 4];
#pragma unroll
    for (int i = 0; i < 8; i++) {
        int row = brow + frag_idx(ty, i);
        float o0[4], o1[4];
#pragma unroll
        for (int j = 0; j < 4; j++) { o0[j] = acc[i][j] + bv0[j]; o1[j] = acc[i][j + 4] + bv1[j]; }
        *(float4*)&C[(size_t)row * N + bcol + tx * 4]      = *(float4*)&o0[0];
        *(float4*)&C[(size_t)row * N + bcol + 64 + tx * 4] = *(float4*)&o1[0];
    }
}

// ---------------- per-row squared norms of Q and K heads ----------------
__global__ __launch_bounds__(256) void norms_kernel()
{
    int gw = (blockIdx.x * 256 + threadIdx.x) >> 5;   // global warp = row in [0, B*H*S)
    int lane = threadIdx.x & 31;
    int z = gw / SEQ;          // b*H + h
    int s = gw % SEQ;
    int b = z / HEADS, h = z % HEADS;
    size_t off = (size_t)(b * SEQ + s) * EMBED + h * HDIM + lane * 2;

    float2 q = *(const float2*)&g_Q[off];
    float2 k = *(const float2*)&g_K[off];
    float qs = q.x * q.x + q.y * q.y;
    float ks = k.x * k.x + k.y * k.y;
#pragma unroll
    for (int o = 16; o > 0; o >>= 1) {
        qs += __shfl_xor_sync(0xffffffffu, qs, o);
        ks += __shfl_xor_sync(0xffffffffu, ks, o);
    }
    if (lane == 0) { g_qsq[gw] = qs; g_ksq[gw] = ks; }
}

// ---------------- scores: logits = -max(|q|^2+|k|^2-2 q.k, 0)/T ----------------
// 128x128 tile per block over (q,k), full D=64 in two 32-chunks
__global__ __launch_bounds__(256) void score_kernel(const float* __restrict__ tempPtr)
{
    __shared__ float Qs[32][128];
    __shared__ float Ks[32][128];
    const int tid = threadIdx.x;
    const int tx = tid % 16, ty = tid / 16;
    const int z = blockIdx.z;
    const int b = z / HEADS, h = z % HEADS;
    const int qbase = blockIdx.x * 128;
    const int kbase = blockIdx.y * 128;

    const float* Qb = g_Q + (size_t)b * SEQ * EMBED + h * HDIM;
    const float* Kb = g_K + (size_t)b * SEQ * EMBED + h * HDIM;

    float acc[8][8];
#pragma unroll
    for (int i = 0; i < 8; i++)
#pragma unroll
        for (int j = 0; j < 8; j++) acc[i][j] = 0.f;

    for (int d0 = 0; d0 < HDIM; d0 += 32) {
#pragma unroll
        for (int it = 0; it < 4; it++) {
            int idx = tid + it * 256;       // 0..1023 float4s
            int r = idx >> 3;               // 0..127
            int c4 = idx & 7;               // 0..7
            float4 vq = *(const float4*)&Qb[(size_t)(qbase + r) * EMBED + d0 + c4 * 4];
            float4 vk = *(const float4*)&Kb[(size_t)(kbase + r) * EMBED + d0 + c4 * 4];
            Qs[c4 * 4 + 0][r] = vq.x; Qs[c4 * 4 + 1][r] = vq.y;
            Qs[c4 * 4 + 2][r] = vq.z; Qs[c4 * 4 + 3][r] = vq.w;
            Ks[c4 * 4 + 0][r] = vk.x; Ks[c4 * 4 + 1][r] = vk.y;
            Ks[c4 * 4 + 2][r] = vk.z; Ks[c4 * 4 + 3][r] = vk.w;
        }
        __syncthreads();
#pragma unroll 8
        for (int d = 0; d < 32; d++) {
            float a[8], bb[8];
            *(float4*)&a[0] = *(const float4*)&Qs[d][ty * 4];
            *(float4*)&a[4] = *(const float4*)&Qs[d][64 + ty * 4];
            *(float4*)&bb[0] = *(const float4*)&Ks[d][tx * 4];
            *(float4*)&bb[4] = *(const float4*)&Ks[d][64 + tx * 4];
#pragma unroll
            for (int i = 0; i < 8; i++)
#pragma unroll
                for (int j = 0; j < 8; j++) acc[i][j] += a[i] * bb[j];
        }
        __syncthreads();
    }

    const float invT = 1.0f / (*tempPtr);
    float kq0[4], kq1[4];
#pragma unroll
    for (int j = 0; j < 4; j++) {
        kq0[j] = g_ksq[(size_t)z * SEQ + kbase + tx * 4 + j];
        kq1[j] = g_ksq[(size_t)z * SEQ + kbase + 64 + tx * 4 + j];
    }
    float* Sb = g_S + (size_t)z * SEQ * SEQ;
#pragma unroll
    for (int i = 0; i < 8; i++) {
        int q = qbase + frag_idx(ty, i);
        float qq = g_qsq[(size_t)z * SEQ + q];
        float o0[4], o1[4];
#pragma unroll
        for (int j = 0; j < 4; j++) {
            float d0v = fmaxf(qq + kq0[j] - 2.f * acc[i][j], 0.f);
            float d1v = fmaxf(qq + kq1[j] - 2.f * acc[i][j + 4], 0.f);
            o0[j] = -d0v * invT;
            o1[j] = -d1v * invT;
        }
        *(float4*)&Sb[(size_t)q * SEQ + kbase + tx * 4]      = *(float4*)&o0[0];
        *(float4*)&Sb[(size_t)q * SEQ + kbase + 64 + tx * 4] = *(float4*)&o1[0];
    }
}

// ---------------- row softmax over 2048 cols ----------------
__global__ __launch_bounds__(256) void softmax_kernel()
{
    __shared__ float redmax[8];
    __shared__ float redsum[8];
    float* row = g_S + (size_t)blockIdx.x * SEQ;
    const int tid = threadIdx.x;
    const int lane = tid & 31, wid = tid >> 5;

    float v[8];
    *(float4*)&v[0] = *(const float4*)&row[tid * 8];
    *(float4*)&v[4] = *(const float4*)&row[tid * 8 + 4];

    float m = v[0];
#pragma unroll
    for (int i = 1; i < 8; i++) m = fmaxf(m, v[i]);
#pragma unroll
    for (int o = 16; o > 0; o >>= 1) m = fmaxf(m, __shfl_xor_sync(0xffffffffu, m, o));
    if (lane == 0) redmax[wid] = m;
    __syncthreads();
    m = redmax[0];
#pragma unroll
    for (int i = 1; i < 8; i++) m = fmaxf(m, redmax[i]);

    float s = 0.f;
#pragma unroll
    for (int i = 0; i < 8; i++) { v[i] = __expf(v[i] - m); s += v[i]; }
#pragma unroll
    for (int o = 16; o > 0; o >>= 1) s += __shfl_xor_sync(0xffffffffu, s, o);
    if (lane == 0) redsum[wid] = s;
    __syncthreads();
    s = 0.f;
#pragma unroll
    for (int i = 0; i < 8; i++) s += redsum[i];

    float inv = 1.0f / s;
#pragma unroll
    for (int i = 0; i < 8; i++) v[i] *= inv;
    *(float4*)&row[tid * 8]     = *(float4*)&v[0];
    *(float4*)&row[tid * 8 + 4] = *(float4*)&v[4];
}

// ---------------- O = P @ V per (b,h): M=2048, N=64, K=2048 ----------------
// 128x64 tile, BK=16, 256 threads, 8x4 per thread
__global__ __launch_bounds__(256) void pv_kernel()
{
    __shared__ float Ps[16][128];
    __shared__ float Vs[16][64];
    const int tid = threadIdx.x;
    const int tx = tid % 16, ty = tid / 16;
    const int z = blockIdx.z;
    const int b = z / HEADS, h = z % HEADS;
    const int mbase = blockIdx.x * 128;

    const float* P  = g_S + (size_t)z * SEQ * SEQ;
    const float* Vb = g_V + (size_t)b * SEQ * EMBED + h * HDIM;
    float*       Ob = g_O + (size_t)b * SEQ * EMBED + h * HDIM;

    float acc[8][4];
#pragma unroll
    for (int i = 0; i < 8; i++)
#pragma unroll
        for (int j = 0; j < 4; j++) acc[i][j] = 0.f;

    for (int k0 = 0; k0 < SEQ; k0 += 16) {
#pragma unroll
        for (int it = 0; it < 2; it++) {
            int idx = tid + it * 256;
            int r = idx >> 2;
            int c4 = idx & 3;
            float4 v = *(const float4*)&P[(size_t)(mbase + r) * SEQ + k0 + c4 * 4];
            Ps[c4 * 4 + 0][r] = v.x; Ps[c4 * 4 + 1][r] = v.y;
            Ps[c4 * 4 + 2][r] = v.z; Ps[c4 * 4 + 3][r] = v.w;
        }
        {
            int r = tid >> 4;        // 0..15
            int c4 = tid & 15;       // 0..15
            *(float4*)&Vs[r][c4 * 4] =
                *(const float4*)&Vb[(size_t)(k0 + r) * EMBED + c4 * 4];
        }
        __syncthreads();
#pragma unroll
        for (int k = 0; k < 16; k++) {
            float a[8], bb[4];
            *(float4*)&a[0] = *(const float4*)&Ps[k][ty * 4];
            *(float4*)&a[4] = *(const float4*)&Ps[k][64 + ty * 4];
            *(float4*)&bb[0] = *(const float4*)&Vs[k][tx * 4];
#pragma unroll
            for (int i = 0; i < 8; i++)
#pragma unroll
                for (int j = 0; j < 4; j++) acc[i][j] += a[i] * bb[j];
        }
        __syncthreads();
    }
#pragma unroll
    for (int i = 0; i < 8; i++) {
        int row = mbase + frag_idx(ty, i);
        *(float4*)&Ob[(size_t)row * EMBED + tx * 4] = *(float4*)&acc[i][0];
    }
}

// ---------------- launcher ----------------
extern "C" void kernel_launch(void* const* d_in, const int* in_sizes, int n_in,
                              void* d_out, int out_size)
{
    const float* query = (const float*)d_in[0];
    const float* wq = (const float*)d_in[1];
    const float* bq = (const float*)d_in[2];
    const float* wk = (const float*)d_in[3];
    const float* bk = (const float*)d_in[4];
    const float* wv = (const float*)d_in[5];
    const float* bv = (const float*)d_in[6];
    const float* wo = (const float*)d_in[7];
    const float* bo = (const float*)d_in[8];
    const float* temperature = (const float*)d_in[9];
    float* out = (float*)d_out;

    float *Qp, *Kp, *Vp, *Op;
    cudaGetSymbolAddress((void**)&Qp, g_Q);
    cudaGetSymbolAddress((void**)&Kp, g_K);
    cudaGetSymbolAddress((void**)&Vp, g_V);
    cudaGetSymbolAddress((void**)&Op, g_O);

    dim3 gProj(EMBED / 128, MROWS / 128);   // (8, 32)
    sgemm_bias_kernel<<<gProj, 256>>>(query, wq, bq, Qp, MROWS, EMBED, EMBED);
    sgemm_bias_kernel<<<gProj, 256>>>(query, wk, bk, Kp, MROWS, EMBED, EMBED);
    sgemm_bias_kernel<<<gProj, 256>>>(query, wv, bv, Vp, MROWS, EMBED, EMBED);

    norms_kernel<<<(B_BATCH * HEADS * SEQ) / 8, 256>>>();

    dim3 gScore(SEQ / 128, SEQ / 128, B_BATCH * HEADS);  // (16,16,32)
    score_kernel<<<gScore, 256>>>(temperature);

    softmax_kernel<<<B_BATCH * HEADS * SEQ, 256>>>();

    dim3 gPV(SEQ / 128, 1, B_BATCH * HEADS);             // (16,1,32)
    pv_kernel<<<gPV, 256>>>();

    sgemm_bias_kernel<<<gProj, 256>>>(Op, wo, bo, out, MROWS, EMBED, EMBED);
}

// round 6
// speedup vs baseline: 3.0318x; 3.0318x over previous
#include <cuda_runtime.h>
#include <cstdint>

#define B_BATCH 2
#define SEQ 2048
#define EMBED 1024
#define HEADS 16
#define HDIM 64
#define MROWS (B_BATCH * SEQ)   // 4096

// ---------------- scratch (device globals: allocation-free) ----------------
__device__ float g_Q[(size_t)MROWS * EMBED];
__device__ float g_K[(size_t)MROWS * EMBED];
__device__ float g_V[(size_t)MROWS * EMBED];
__device__ float g_O[(size_t)MROWS * EMBED];
__device__ float g_Wt[(size_t)4 * EMBED * EMBED];              // transposed weights (tf32)
__device__ float g_Vt[(size_t)B_BATCH * HEADS * HDIM * SEQ];   // V transposed per head (tf32)
__device__ float g_qsq[(size_t)B_BATCH * HEADS * SEQ];
__device__ float g_ksq[(size_t)B_BATCH * HEADS * SEQ];

// ======================= helpers =======================
__device__ __forceinline__ uint32_t smem_u32(const void* p) {
    uint32_t a;
    asm("{ .reg .u64 t; cvta.to.shared.u64 t, %1; cvt.u32.u64 %0, t; }" : "=r"(a) : "l"(p));
    return a;
}
__device__ __forceinline__ float to_tf32(float x) {
    float r; asm("cvt.rna.tf32.f32 %0, %1;" : "=f"(r) : "f"(x)); return r;
}
__device__ __forceinline__ void cp_async16(uint32_t dst, const void* src) {
    asm volatile("cp.async.cg.shared.global [%0], [%1], 16;" :: "r"(dst), "l"(src));
}
#define CP_COMMIT() asm volatile("cp.async.commit_group;" ::: "memory")
#define CP_WAIT0()  asm volatile("cp.async.wait_group 0;" ::: "memory")

// mma.sync m16n8k8 tf32: D += A*B  (A row-major m16k8, B col-major k8n8)
__device__ __forceinline__ void mma_tf32(float* d, const uint32_t* a, const uint32_t* b) {
    asm volatile(
        "mma.sync.aligned.m16n8k8.row.col.f32.tf32.tf32.f32 "
        "{%0,%1,%2,%3}, {%4,%5,%6,%7}, {%8,%9}, {%0,%1,%2,%3};"
        : "+f"(d[0]), "+f"(d[1]), "+f"(d[2]), "+f"(d[3])
        : "r"(a[0]), "r"(a[1]), "r"(a[2]), "r"(a[3]), "r"(b[0]), "r"(b[1]));
}
__device__ __forceinline__ uint32_t ldsf(const float* p) { return __float_as_uint(*p); }

// ======================= transpose weights (+tf32 round) =======================
__global__ __launch_bounds__(256) void transpose_w_kernel(
    const float* __restrict__ wq, const float* __restrict__ wk,
    const float* __restrict__ wv, const float* __restrict__ wo)
{
    __shared__ float t[32][33];
    const int z = blockIdx.z;
    const float* W = (z == 0) ? wq : (z == 1) ? wk : (z == 2) ? wv : wo;
    float* Out = g_Wt + (size_t)z * EMBED * EMBED;
    const int k0 = blockIdx.x * 32, n0 = blockIdx.y * 32;
    const int tx = threadIdx.x & 31, ty = threadIdx.x >> 5;
#pragma unroll
    for (int i = 0; i < 4; i++)
        t[ty + i * 8][tx] = W[(size_t)(k0 + ty + i * 8) * EMBED + n0 + tx];
    __syncthreads();
#pragma unroll
    for (int i = 0; i < 4; i++)
        Out[(size_t)(n0 + ty + i * 8) * EMBED + k0 + tx] = to_tf32(t[tx][ty + i * 8]);
}

// ======================= transpose V per head (+tf32 round) =======================
__global__ __launch_bounds__(256) void transpose_v_kernel()
{
    __shared__ float t[32][33];
    const int b = blockIdx.z;
    const int e0 = blockIdx.x * 32, s0 = blockIdx.y * 32;
    const int tx = threadIdx.x & 31, ty = threadIdx.x >> 5;
#pragma unroll
    for (int i = 0; i < 4; i++)
        t[ty + i * 8][tx] = g_V[(size_t)(b * SEQ + s0 + ty + i * 8) * EMBED + e0 + tx];
    __syncthreads();
#pragma unroll
    for (int i = 0; i < 4; i++) {
        int e = e0 + ty + i * 8;
        int s = s0 + tx;
        g_Vt[(size_t)(b * HEADS + (e >> 6)) * HDIM * SEQ + (size_t)(e & 63) * SEQ + s] =
            to_tf32(t[tx][ty + i * 8]);
    }
}

// ======================= per-row squared norms =======================
__global__ __launch_bounds__(256) void norms_kernel()
{
    int gw = (blockIdx.x * 256 + threadIdx.x) >> 5;
    int lane = threadIdx.x & 31;
    int z = gw / SEQ, s = gw % SEQ;
    int b = z / HEADS, h = z % HEADS;
    size_t off = (size_t)(b * SEQ + s) * EMBED + h * HDIM + lane * 2;
    float2 q = *(const float2*)&g_Q[off];
    float2 k = *(const float2*)&g_K[off];
    float qs = q.x * q.x + q.y * q.y;
    float ks = k.x * k.x + k.y * k.y;
#pragma unroll
    for (int o = 16; o > 0; o >>= 1) {
        qs += __shfl_xor_sync(0xffffffffu, qs, o);
        ks += __shfl_xor_sync(0xffffffffu, ks, o);
    }
    if (lane == 0) { g_qsq[gw] = qs; g_ksq[gw] = ks; }
}

// ======================= tf32 mma.sync projection GEMM =======================
// C[4096,1024] = A[4096,1024] @ Bt^T + bias. Block 128x128, BK=32, 8 warps (64x32 each).
// Smem per stage: As[128][36], Bs[128][36] floats; 2 stages; dyn smem 73728 B.
#define PROJ_SMEM (4 * 128 * 36 * 4)

template <bool ROUND>
__global__ __launch_bounds__(256) void proj_mma_kernel(
    const float* __restrict__ A, const float* __restrict__ Bt,
    const float* __restrict__ bias, float* __restrict__ C)
{
    extern __shared__ __align__(16) float sm[];
    float* Abuf[2] = { sm,               sm + 128 * 36 };
    float* Bbuf[2] = { sm + 2 * 128 * 36, sm + 3 * 128 * 36 };
    const uint32_t sA[2] = { smem_u32(Abuf[0]), smem_u32(Abuf[1]) };
    const uint32_t sB[2] = { smem_u32(Bbuf[0]), smem_u32(Bbuf[1]) };

    const int tid = threadIdx.x, lane = tid & 31, warp = tid >> 5;
    const int g = lane >> 2, tg = lane & 3;
    const int m0 = blockIdx.y * 128, n0 = blockIdx.x * 128;
    const int mw = (warp >> 2) * 64, nw = (warp & 3) * 32;

    float acc[4][4][4];
#pragma unroll
    for (int mi = 0; mi < 4; mi++)
#pragma unroll
        for (int ni = 0; ni < 4; ni++)
#pragma unroll
            for (int c = 0; c < 4; c++) acc[mi][ni][c] = 0.f;

    // issue stage kc into buffer buf
    auto issue = [&](int kc, int buf) {
        const int k0 = kc * 32;
#pragma unroll
        for (int it = 0; it < 4; it++) {
            int idx = tid + it * 256;
            int r = idx >> 3, c = idx & 7;
            cp_async16(sA[buf] + r * 144 + c * 16, &A[(size_t)(m0 + r) * EMBED + k0 + c * 4]);
            cp_async16(sB[buf] + r * 144 + c * 16, &Bt[(size_t)(n0 + r) * EMBED + k0 + c * 4]);
        }
        CP_COMMIT();
    };

    issue(0, 0);
    for (int kc = 0; kc < 32; kc++) {
        CP_WAIT0();
        __syncthreads();
        if (kc + 1 < 32) issue(kc + 1, (kc + 1) & 1);
        const float* As = Abuf[kc & 1];
        const float* Bs = Bbuf[kc & 1];
#pragma unroll
        for (int ks = 0; ks < 4; ks++) {
            const int k = ks * 8;
            uint32_t af[4][4], bf[4][2];
#pragma unroll
            for (int mi = 0; mi < 4; mi++) {
                const float* ap = &As[(mw + mi * 16 + g) * 36 + k + tg];
                af[mi][0] = ldsf(ap);
                af[mi][1] = ldsf(ap + 8 * 36);
                af[mi][2] = ldsf(ap + 4);
                af[mi][3] = ldsf(ap + 8 * 36 + 4);
            }
#pragma unroll
            for (int ni = 0; ni < 4; ni++) {
                const float* bp = &Bs[(nw + ni * 8 + g) * 36 + k + tg];
                bf[ni][0] = ldsf(bp);
                bf[ni][1] = ldsf(bp + 4);
            }
#pragma unroll
            for (int mi = 0; mi < 4; mi++)
#pragma unroll
                for (int ni = 0; ni < 4; ni++)
                    mma_tf32(acc[mi][ni], af[mi], bf[ni]);
        }
        __syncthreads();
    }

#pragma unroll
    for (int mi = 0; mi < 4; mi++)
#pragma unroll
        for (int ni = 0; ni < 4; ni++) {
            int row = m0 + mw + mi * 16 + g;
            int col = n0 + nw + ni * 8 + tg * 2;
            float b0 = bias[col], b1 = bias[col + 1];
            float2 v0, v1;
            v0.x = acc[mi][ni][0] + b0; v0.y = acc[mi][ni][1] + b1;
            v1.x = acc[mi][ni][2] + b0; v1.y = acc[mi][ni][3] + b1;
            if (ROUND) {
                v0.x = to_tf32(v0.x); v0.y = to_tf32(v0.y);
                v1.x = to_tf32(v1.x); v1.y = to_tf32(v1.y);
            }
            *(float2*)&C[(size_t)row * EMBED + col] = v0;
            *(float2*)&C[(size_t)(row + 8) * EMBED + col] = v1;
        }
}

// ======================= fused attention (tf32 mma.sync) =======================
// Per block: one (b,h), one 128-row q-tile; 16 k-tiles of 128.
// Smem (floats): Qs[128][68] | Ks[128][68] | Vts[64][132] | Ps[128][132] | ksq[128] | lsum[128][2]
#define SM_Q    0
#define SM_K    34816
#define SM_VT   69632
#define SM_P    103424
#define SM_KSQ  171008
#define SM_LSUM 171520
#define SM_ATT_BYTES 172544

__global__ __launch_bounds__(256, 1) void attention_kernel(const float* __restrict__ tempPtr)
{
    extern __shared__ __align__(16) char smc[];
    float* Qs  = (float*)(smc + SM_Q);
    float* Ks  = (float*)(smc + SM_K);
    float* Vts = (float*)(smc + SM_VT);
    float* Ps  = (float*)(smc + SM_P);
    float* ksq = (float*)(smc + SM_KSQ);
    float* lsum = (float*)(smc + SM_LSUM);
    const uint32_t sQ = smem_u32(Qs), sK = smem_u32(Ks), sVT = smem_u32(Vts);

    const int tid = threadIdx.x, lane = tid & 31, warp = tid >> 5;
    const int g = lane >> 2, tg = lane & 3;
    const int mw = (warp >> 1) * 32;           // S/O m-offset of this warp
    const int nhalf = warp & 1;
    const int nw = nhalf * 64;                 // S n-offset
    const int nwo = nhalf * 32;                // O n-offset

    const int z = blockIdx.y;                  // b*HEADS + h
    const int b = z / HEADS, h = z % HEADS;
    const int q0 = blockIdx.x * 128;
    const float invT = 1.0f / (*tempPtr);

    // Q tile load (once): 128 rows x 64 cols
#pragma unroll
    for (int it = 0; it < 8; it++) {
        int idx = tid + it * 256;
        int r = idx >> 4, c = idx & 15;
        cp_async16(sQ + r * 272 + c * 16,
                   &g_Q[(size_t)(b * SEQ + q0 + r) * EMBED + h * HDIM + c * 4]);
    }
    CP_COMMIT();

    // per-thread q norms for its 4 rows
    float qqv[4];
#pragma unroll
    for (int mi = 0; mi < 2; mi++) {
        qqv[mi * 2 + 0] = g_qsq[(size_t)z * SEQ + q0 + mw + mi * 16 + g];
        qqv[mi * 2 + 1] = g_qsq[(size_t)z * SEQ + q0 + mw + mi * 16 + g + 8];
    }

    float oacc[2][4][4];
#pragma unroll
    for (int mi = 0; mi < 2; mi++)
#pragma unroll
        for (int ni = 0; ni < 4; ni++)
#pragma unroll
            for (int c = 0; c < 4; c++) oacc[mi][ni][c] = 0.f;
    float rsum[4] = {0.f, 0.f, 0.f, 0.f};

    for (int kt = 0; kt < 16; kt++) {
        const int kk0 = kt * 128;
        __syncthreads();   // all warps done reading Ks/Vts/Ps of previous iter
        // K tile [128][64], Vt tile [64][128]
#pragma unroll
        for (int it = 0; it < 8; it++) {
            int idx = tid + it * 256;
            {
                int r = idx >> 4, c = idx & 15;
                cp_async16(sK + r * 272 + c * 16,
                           &g_K[(size_t)(b * SEQ + kk0 + r) * EMBED + h * HDIM + c * 4]);
            }
            {
                int r = idx >> 5, c = idx & 31;
                cp_async16(sVT + r * 528 + c * 16,
                           &g_Vt[(size_t)z * HDIM * SEQ + (size_t)r * SEQ + kk0 + c * 4]);
            }
        }
        CP_COMMIT();
        if (tid < 32) {
            float4 v = ((const float4*)&g_ksq[(size_t)z * SEQ + kk0])[tid];
            ((float4*)ksq)[tid] = v;
        }
        CP_WAIT0();
        __syncthreads();

        // ---- S = Q @ K^T (warp: 32x64) ----
        float sacc[2][8][4];
#pragma unroll
        for (int mi = 0; mi < 2; mi++)
#pragma unroll
            for (int nj = 0; nj < 8; nj++)
#pragma unroll
                for (int c = 0; c < 4; c++) sacc[mi][nj][c] = 0.f;
#pragma unroll
        for (int ks = 0; ks < 8; ks++) {
            const int k = ks * 8;
            uint32_t af[2][4], bf[8][2];
#pragma unroll
            for (int mi = 0; mi < 2; mi++) {
                const float* ap = &Qs[(mw + mi * 16 + g) * 68 + k + tg];
                af[mi][0] = ldsf(ap);
                af[mi][1] = ldsf(ap + 8 * 68);
                af[mi][2] = ldsf(ap + 4);
                af[mi][3] = ldsf(ap + 8 * 68 + 4);
            }
#pragma unroll
            for (int nj = 0; nj < 8; nj++) {
                const float* bp = &Ks[(nw + nj * 8 + g) * 68 + k + tg];
                bf[nj][0] = ldsf(bp);
                bf[nj][1] = ldsf(bp + 4);
            }
#pragma unroll
            for (int mi = 0; mi < 2; mi++)
#pragma unroll
                for (int nj = 0; nj < 8; nj++)
                    mma_tf32(sacc[mi][nj], af[mi], bf[nj]);
        }

        // ---- epilogue: p = exp(-max(qq+kk-2s,0)/T), write P ----
#pragma unroll
        for (int mi = 0; mi < 2; mi++) {
            const int rlo = mw + mi * 16 + g, rhi = rlo + 8;
            const float qlo = qqv[mi * 2], qhi = qqv[mi * 2 + 1];
#pragma unroll
            for (int nj = 0; nj < 8; nj++) {
                const int col = nw + nj * 8 + tg * 2;
                const float kc0 = ksq[col], kc1 = ksq[col + 1];
                float p00 = __expf(-fmaxf(qlo + kc0 - 2.f * sacc[mi][nj][0], 0.f) * invT);
                float p01 = __expf(-fmaxf(qlo + kc1 - 2.f * sacc[mi][nj][1], 0.f) * invT);
                float p10 = __expf(-fmaxf(qhi + kc0 - 2.f * sacc[mi][nj][2], 0.f) * invT);
                float p11 = __expf(-fmaxf(qhi + kc1 - 2.f * sacc[mi][nj][3], 0.f) * invT);
                rsum[mi * 2 + 0] += p00 + p01;
                rsum[mi * 2 + 1] += p10 + p11;
                float2 w0 = { to_tf32(p00), to_tf32(p01) };
                float2 w1 = { to_tf32(p10), to_tf32(p11) };
                *(float2*)&Ps[rlo * 132 + col] = w0;
                *(float2*)&Ps[rhi * 132 + col] = w1;
            }
        }
        __syncthreads();

        // ---- O += P @ V (warp: 32x32, k=128) ----
#pragma unroll
        for (int ks = 0; ks < 16; ks++) {
            const int k = ks * 8;
            uint32_t paf[2][4], vbf[4][2];
#pragma unroll
            for (int mi = 0; mi < 2; mi++) {
                const float* ap = &Ps[(mw + mi * 16 + g) * 132 + k + tg];
                paf[mi][0] = ldsf(ap);
                paf[mi][1] = ldsf(ap + 8 * 132);
                paf[mi][2] = ldsf(ap + 4);
                paf[mi][3] = ldsf(ap + 8 * 132 + 4);
            }
#pragma unroll
            for (int ni = 0; ni < 4; ni++) {
                const float* bp = &Vts[(nwo + ni * 8 + g) * 132 + k + tg];
                vbf[ni][0] = ldsf(bp);
                vbf[ni][1] = ldsf(bp + 4);
            }
#pragma unroll
            for (int mi = 0; mi < 2; mi++)
#pragma unroll
                for (int ni = 0; ni < 4; ni++)
                    mma_tf32(oacc[mi][ni], paf[mi], vbf[ni]);
        }
    }

    // ---- row-sum reduce across tg lanes and n-halves ----
#pragma unroll
    for (int i = 0; i < 4; i++) {
        rsum[i] += __shfl_xor_sync(0xffffffffu, rsum[i], 1);
        rsum[i] += __shfl_xor_sync(0xffffffffu, rsum[i], 2);
    }
    __syncthreads();   // Ps/lsum region reuse safety
    if (tg == 0) {
#pragma unroll
        for (int mi = 0; mi < 2; mi++) {
            lsum[(mw + mi * 16 + g) * 2 + nhalf]     = rsum[mi * 2 + 0];
            lsum[(mw + mi * 16 + g + 8) * 2 + nhalf] = rsum[mi * 2 + 1];
        }
    }
    __syncthreads();

    float linv[4];
#pragma unroll
    for (int mi = 0; mi < 2; mi++) {
        int rlo = mw + mi * 16 + g, rhi = rlo + 8;
        linv[mi * 2 + 0] = 1.f / (lsum[rlo * 2] + lsum[rlo * 2 + 1]);
        linv[mi * 2 + 1] = 1.f / (lsum[rhi * 2] + lsum[rhi * 2 + 1]);
    }

#pragma unroll
    for (int mi = 0; mi < 2; mi++)
#pragma unroll
        for (int ni = 0; ni < 4; ni++) {
            int rlo = mw + mi * 16 + g, rhi = rlo + 8;
            int col = nwo + ni * 8 + tg * 2;
            float2 w0, w1;
            w0.x = to_tf32(oacc[mi][ni][0] * linv[mi * 2]);
            w0.y = to_tf32(oacc[mi][ni][1] * linv[mi * 2]);
            w1.x = to_tf32(oacc[mi][ni][2] * linv[mi * 2 + 1]);
            w1.y = to_tf32(oacc[mi][ni][3] * linv[mi * 2 + 1]);
            *(float2*)&g_O[(size_t)(b * SEQ + q0 + rlo) * EMBED + h * HDIM + col] = w0;
            *(float2*)&g_O[(size_t)(b * SEQ + q0 + rhi) * EMBED + h * HDIM + col] = w1;
        }
}

// ======================= launcher =======================
extern "C" void kernel_launch(void* const* d_in, const int* in_sizes, int n_in,
                              void* d_out, int out_size)
{
    const float* query = (const float*)d_in[0];
    const float* wq = (const float*)d_in[1];
    const float* bq = (const float*)d_in[2];
    const float* wk = (const float*)d_in[3];
    const float* bk = (const float*)d_in[4];
    const float* wv = (const float*)d_in[5];
    const float* bv = (const float*)d_in[6];
    const float* wo = (const float*)d_in[7];
    const float* bo = (const float*)d_in[8];
    const float* temperature = (const float*)d_in[9];
    float* out = (float*)d_out;

    cudaFuncSetAttribute(attention_kernel,
                         cudaFuncAttributeMaxDynamicSharedMemorySize, SM_ATT_BYTES);
    cudaFuncSetAttribute(proj_mma_kernel<true>,
                         cudaFuncAttributeMaxDynamicSharedMemorySize, PROJ_SMEM);
    cudaFuncSetAttribute(proj_mma_kernel<false>,
                         cudaFuncAttributeMaxDynamicSharedMemorySize, PROJ_SMEM);

    float *Qp, *Kp, *Vp, *Op, *Wtp;
    cudaGetSymbolAddress((void**)&Qp, g_Q);
    cudaGetSymbolAddress((void**)&Kp, g_K);
    cudaGetSymbolAddress((void**)&Vp, g_V);
    cudaGetSymbolAddress((void**)&Op, g_O);
    cudaGetSymbolAddress((void**)&Wtp, g_Wt);

    dim3 gTW(EMBED / 32, EMBED / 32, 4);
    transpose_w_kernel<<<gTW, 256>>>(wq, wk, wv, wo);

    dim3 gProj(EMBED / 128, MROWS / 128);     // (8, 32)
    proj_mma_kernel<true><<<gProj, 256, PROJ_SMEM>>>(query, Wtp + 0 * (size_t)EMBED * EMBED, bq, Qp);
    proj_mma_kernel<true><<<gProj, 256, PROJ_SMEM>>>(query, Wtp + 1 * (size_t)EMBED * EMBED, bk, Kp);
    proj_mma_kernel<false><<<gProj, 256, PROJ_SMEM>>>(query, Wtp + 2 * (size_t)EMBED * EMBED, bv, Vp);

    norms_kernel<<<(B_BATCH * HEADS * SEQ) / 8, 256>>>();

    dim3 gTV(EMBED / 32, SEQ / 32, B_BATCH);
    transpose_v_kernel<<<gTV, 256>>>();

    dim3 gAtt(SEQ / 128, B_BATCH * HEADS);    // (16, 32)
    attention_kernel<<<gAtt, 256, SM_ATT_BYTES>>>(temperature);

    proj_mma_kernel<false><<<gProj, 256, PROJ_SMEM>>>(Op, Wtp + 3 * (size_t)EMBED * EMBED, bo, out);
}